// round 1
// baseline (speedup 1.0000x reference)
#include <cuda_runtime.h>
#include <cstdint>

// Problem constants (fixed by reference)
#define NN    16384   // n_nodes
#define D_IN  128
#define D_H   64
#define BB    4096    // minibatch
// ppr row = 16384 floats = 4096 float4

// Device scratch (no allocations allowed)
__device__ float g_enc[NN * D_H];    // 4 MiB
__device__ int   g_idx[BB];

// ---------------------------------------------------------------------------
// Kernel 1: decode idx (handles both int32 and int64 on-disk layouts).
// int64 little-endian with values in [0, 16384) => every odd int32 word == 0.
// Genuine int32 data has ~0 probability of 2048 consecutive zero odd words.
// Only reads the first 16 KiB for detection (safe for either layout).
// ---------------------------------------------------------------------------
__global__ void decode_idx_kernel(const int* __restrict__ idx32) {
    __shared__ int s_is64;
    int tid = threadIdx.x;
    if (tid == 0) s_is64 = 1;
    __syncthreads();
    for (int i = tid; i < BB / 2; i += blockDim.x) {
        if (idx32[2 * i + 1] != 0) s_is64 = 0;   // benign race: all writers write 0
    }
    __syncthreads();
    if (s_is64) {
        for (int i = tid; i < BB; i += blockDim.x) g_idx[i] = idx32[2 * i];
    } else {
        for (int i = tid; i < BB; i += blockDim.x) g_idx[i] = idx32[i];
    }
}

// ---------------------------------------------------------------------------
// Kernel 2: enc = X @ W + b   -> g_enc [NN, 64]
// 256 threads, 32 rows per block. W (128x64 = 32KB) + 32 X rows (16KB) in smem.
// Thread: c = tid&63, r0 = tid>>6, computes rows r0, r0+4, ..., r0+28.
// ---------------------------------------------------------------------------
__global__ void __launch_bounds__(256) enc_kernel(const float* __restrict__ X,
                                                  const float* __restrict__ W,
                                                  const float* __restrict__ b) {
    __shared__ float sW[D_IN * D_H];   // 32 KiB
    __shared__ float sX[32 * D_IN];    // 16 KiB
    const int tid = threadIdx.x;

    for (int i = tid; i < D_IN * D_H; i += 256) sW[i] = W[i];
    const int row0 = blockIdx.x * 32;
    for (int i = tid; i < 32 * D_IN; i += 256) sX[i] = X[(size_t)row0 * D_IN + i];
    __syncthreads();

    const int c  = tid & 63;
    const int r0 = tid >> 6;           // 0..3
    const float bc = b[c];
    float acc[8];
#pragma unroll
    for (int a = 0; a < 8; a++) acc[a] = bc;

#pragma unroll 4
    for (int k = 0; k < D_IN; k++) {
        const float w = sW[k * D_H + c];
#pragma unroll
        for (int a = 0; a < 8; a++)
            acc[a] += sX[(r0 + 4 * a) * D_IN + k] * w;
    }
#pragma unroll
    for (int a = 0; a < 8; a++)
        g_enc[(size_t)(row0 + r0 + 4 * a) * D_H + c] = acc[a];
}

// ---------------------------------------------------------------------------
// Kernel 3: out[i,:] = ppr[idx[i],:] @ enc  exploiting TOPK=128 sparsity.
// One block (4 warps, 128 thr) per output row. Each warp scans 1/4 of the
// 16384-float row as float4 (streaming loads, batched x4 for MLP). Nonzeros
// are found via ballot, broadcast via shfl; each lane accumulates 2 output
// columns (lane, lane+32). Final smem reduction across warps.
// ---------------------------------------------------------------------------
__global__ void __launch_bounds__(128) gather_kernel(const float* __restrict__ ppr,
                                                     float* __restrict__ out) {
    const int i    = blockIdx.x;
    const int lane = threadIdx.x & 31;
    const int warp = threadIdx.x >> 5;
    const int row  = g_idx[i];

    const float4* rowp = reinterpret_cast<const float4*>(ppr) + (size_t)row * (NN / 4);
    const int base = warp * (NN / 4 / 4);   // 1024 float4 per warp

    float acc0 = 0.0f, acc1 = 0.0f;

    for (int it = 0; it < 32; it += 4) {
        float4 buf[4];
#pragma unroll
        for (int u = 0; u < 4; u++)
            buf[u] = __ldcs(rowp + base + (it + u) * 32 + lane);

#pragma unroll
        for (int u = 0; u < 4; u++) {
            const int j0 = (base + (it + u) * 32 + lane) * 4;
            float vs[4] = {buf[u].x, buf[u].y, buf[u].z, buf[u].w};
#pragma unroll
            for (int e = 0; e < 4; e++) {
                unsigned m = __ballot_sync(0xffffffffu, vs[e] != 0.0f);
                while (m) {
                    const int src = __ffs(m) - 1;
                    m &= m - 1;
                    const float v = __shfl_sync(0xffffffffu, vs[e], src);
                    const int   j = __shfl_sync(0xffffffffu, j0 + e, src);
                    const float* er = g_enc + (size_t)j * D_H;
                    acc0 += v * __ldg(er + lane);
                    acc1 += v * __ldg(er + lane + 32);
                }
            }
        }
    }

    __shared__ float red[4][D_H];
    red[warp][lane]      = acc0;
    red[warp][lane + 32] = acc1;
    __syncthreads();
    if (threadIdx.x < D_H) {
        const int c = threadIdx.x;
        out[(size_t)i * D_H + c] = red[0][c] + red[1][c] + red[2][c] + red[3][c];
    }
}

// ---------------------------------------------------------------------------
extern "C" void kernel_launch(void* const* d_in, const int* in_sizes, int n_in,
                              void* d_out, int out_size) {
    const float* X   = (const float*)d_in[0];
    const float* ppr = (const float*)d_in[1];
    const float* W   = (const float*)d_in[2];
    const float* b   = (const float*)d_in[3];
    const int*   idx = (const int*)d_in[4];   // decoded in-kernel (int32 or int64)
    float* out = (float*)d_out;

    decode_idx_kernel<<<1, 256>>>(idx);
    enc_kernel<<<NN / 32, 256>>>(X, W, b);
    gather_kernel<<<BB, 128>>>(ppr, out);
}

// round 2
// speedup vs baseline: 1.0386x; 1.0386x over previous
#include <cuda_runtime.h>
#include <cstdint>

// Problem constants (fixed by reference)
#define NN    16384   // n_nodes
#define D_IN  128
#define D_H   64
#define BB    4096    // minibatch

// Device scratch (no allocations allowed)
__device__ float g_enc[NN * D_H];    // 4 MiB
__device__ int   g_idx[BB];

// ---------------------------------------------------------------------------
// Kernel 1: enc = X @ W + b -> g_enc [NN, 64], with idx decode fused in as an
// extra block (blockIdx == NN/32). Decode handles int64 vs int32 layouts:
// int64 little-endian with values in [0,16384) => every odd int32 word == 0.
// Only the first 16 KiB are read for detection (safe for either layout).
// ---------------------------------------------------------------------------
__global__ void __launch_bounds__(256) enc_kernel(const float* __restrict__ X,
                                                  const float* __restrict__ W,
                                                  const float* __restrict__ b,
                                                  const int* __restrict__ idx32) {
    if (blockIdx.x == NN / 32) {
        // ---- idx decode block ----
        __shared__ int s_is64;
        const int tid = threadIdx.x;
        if (tid == 0) s_is64 = 1;
        __syncthreads();
        for (int i = tid; i < BB / 2; i += 256)
            if (idx32[2 * i + 1] != 0) s_is64 = 0;   // benign race: all write 0
        __syncthreads();
        if (s_is64) {
            for (int i = tid; i < BB; i += 256) g_idx[i] = idx32[2 * i];
        } else {
            for (int i = tid; i < BB; i += 256) g_idx[i] = idx32[i];
        }
        return;
    }

    __shared__ float sW[D_IN * D_H];   // 32 KiB
    __shared__ float sX[32 * D_IN];    // 16 KiB
    const int tid = threadIdx.x;

    for (int i = tid; i < D_IN * D_H; i += 256) sW[i] = W[i];
    const int row0 = blockIdx.x * 32;
    for (int i = tid; i < 32 * D_IN; i += 256) sX[i] = X[(size_t)row0 * D_IN + i];
    __syncthreads();

    const int c  = tid & 63;
    const int r0 = tid >> 6;           // 0..3
    const float bc = b[c];
    float acc[8];
#pragma unroll
    for (int a = 0; a < 8; a++) acc[a] = bc;

#pragma unroll 4
    for (int k = 0; k < D_IN; k++) {
        const float w = sW[k * D_H + c];
#pragma unroll
        for (int a = 0; a < 8; a++)
            acc[a] += sX[(r0 + 4 * a) * D_IN + k] * w;
    }
#pragma unroll
    for (int a = 0; a < 8; a++)
        g_enc[(size_t)(row0 + r0 + 4 * a) * D_H + c] = acc[a];
}

// ---------------------------------------------------------------------------
// Kernel 2: out[i,:] = ppr[idx[i],:] @ enc  exploiting TOPK=128 sparsity.
// One block (4 warps) per output row; each warp streams 1/4 of the 64KB row.
// Phase 1: lean scan — 8 uint4 loads in flight per lane (MLP=8), integer-OR
//          zero test per float4 (valid: values are nonneg, zeros are exact
//          +0.0f), rare nonzeros appended to a per-warp smem list.
// Phase 2: replay list once; each lane accumulates 2 output columns from the
//          L2-resident g_enc.
// ---------------------------------------------------------------------------
__global__ void __launch_bounds__(128) gather_kernel(const float* __restrict__ ppr,
                                                     float* __restrict__ out) {
    __shared__ float vbuf[4][160];
    __shared__ int   jbuf[4][160];
    __shared__ int   cnt[4];
    __shared__ float red[4][D_H];

    const int i    = blockIdx.x;
    const int lane = threadIdx.x & 31;
    const int warp = threadIdx.x >> 5;

    if (lane == 0) cnt[warp] = 0;
    __syncwarp();

    const int row = g_idx[i];
    const uint4* rowp = reinterpret_cast<const uint4*>(ppr) + (size_t)row * (NN / 4);
    const int base = warp * (NN / 16);   // 1024 float4 per warp

    // ---- Phase 1: stream + extract nonzeros ----
    for (int it = 0; it < 32; it += 8) {
        uint4 buf[8];
#pragma unroll
        for (int u = 0; u < 8; u++)
            buf[u] = __ldcs(rowp + base + (it + u) * 32 + lane);

#pragma unroll
        for (int u = 0; u < 8; u++) {
            const uint4 q = buf[u];
            if (q.x | q.y | q.z | q.w) {
                const int j0 = (base + (it + u) * 32 + lane) * 4;
                const float fx = __uint_as_float(q.x);
                const float fy = __uint_as_float(q.y);
                const float fz = __uint_as_float(q.z);
                const float fw = __uint_as_float(q.w);
                if (q.x) { int p = atomicAdd(&cnt[warp], 1); if (p < 160) { jbuf[warp][p] = j0;     vbuf[warp][p] = fx; } }
                if (q.y) { int p = atomicAdd(&cnt[warp], 1); if (p < 160) { jbuf[warp][p] = j0 + 1; vbuf[warp][p] = fy; } }
                if (q.z) { int p = atomicAdd(&cnt[warp], 1); if (p < 160) { jbuf[warp][p] = j0 + 2; vbuf[warp][p] = fz; } }
                if (q.w) { int p = atomicAdd(&cnt[warp], 1); if (p < 160) { jbuf[warp][p] = j0 + 3; vbuf[warp][p] = fw; } }
            }
        }
    }
    __syncwarp();

    // ---- Phase 2: replay nonzero list ----
    float acc0 = 0.0f, acc1 = 0.0f;
    const int n = min(cnt[warp], 160);
    for (int k = 0; k < n; k++) {
        const float v = vbuf[warp][k];
        const float* er = g_enc + (size_t)jbuf[warp][k] * D_H;
        acc0 += v * __ldg(er + lane);
        acc1 += v * __ldg(er + lane + 32);
    }

    red[warp][lane]      = acc0;
    red[warp][lane + 32] = acc1;
    __syncthreads();
    if (threadIdx.x < D_H) {
        const int c = threadIdx.x;
        out[(size_t)i * D_H + c] = red[0][c] + red[1][c] + red[2][c] + red[3][c];
    }
}

// ---------------------------------------------------------------------------
extern "C" void kernel_launch(void* const* d_in, const int* in_sizes, int n_in,
                              void* d_out, int out_size) {
    const float* X   = (const float*)d_in[0];
    const float* ppr = (const float*)d_in[1];
    const float* W   = (const float*)d_in[2];
    const float* b   = (const float*)d_in[3];
    const int*   idx = (const int*)d_in[4];   // decoded in-kernel (int32 or int64)
    float* out = (float*)d_out;

    enc_kernel<<<NN / 32 + 1, 256>>>(X, W, b, idx);
    gather_kernel<<<BB, 128>>>(ppr, out);
}